// round 2
// baseline (speedup 1.0000x reference)
#include <cuda_runtime.h>
#include <cstdint>

// Problem constants
#define TT   2048
#define HH   512
#define NB   32
#define II   88
#define TH   (TT*HH)          // 1048576 (per-batch stride in hiddens)
#define NTOT (NB*TH)          // 33554432 (one hiddens tensor)
#define NT   (NB*TT)          // 65536 rows in xproj GEMM
#define NCTA 128

// Device scratch (static allocations are the sanctioned workaround)
__device__ float    g_xp[NT * HH];   // xproj [n][t][h] flattened as [nt][h], 128 MB
__device__ unsigned g_bar;           // global barrier counter (monotone per launch)

// ---------------------------------------------------------------------------
// Phase 1: xproj[nt][h] = sum_i x[nt][i] * W_ih[h][i] + b_ih[h]
// Block: 512 threads (one per h). Each block handles 32 nt rows.
// W_ih row cached in registers (88 floats), x rows staged in smem (broadcast).
// ---------------------------------------------------------------------------
__global__ void __launch_bounds__(512, 1) xproj_kernel(
    const float* __restrict__ x,
    const float* __restrict__ W_ih,
    const float* __restrict__ b_ih)
{
    __shared__ float xs[32][II];
    const int h   = threadIdx.x;          // 0..511
    const int nt0 = blockIdx.x * 32;

    float w[II];
#pragma unroll
    for (int i = 0; i < II; i++) w[i] = W_ih[h * II + i];
    const float b = b_ih[h];

    // stage 32 x-rows (32*88 floats) into smem
    for (int f = threadIdx.x; f < 32 * II; f += 512) {
        xs[f / II][f % II] = x[nt0 * II + f];
    }
    __syncthreads();

#pragma unroll 1
    for (int j = 0; j < 32; j++) {
        float s = b;
#pragma unroll
        for (int i = 0; i < II; i++) s += w[i] * xs[j][i];
        g_xp[(nt0 + j) * HH + h] = s;
    }
}

// ---------------------------------------------------------------------------
// Phase 2: h0 = initial + xproj[:,0]; also resets the global barrier counter.
// ---------------------------------------------------------------------------
__global__ void h0_kernel(const float* __restrict__ initial,
                          float* __restrict__ out, int dup)
{
    const int n = blockIdx.x;     // 0..31
    const int h = threadIdx.x;    // 0..511
    float v = initial[n * HH + h] + g_xp[(n * TT + 0) * HH + h];
    out[n * TH + 0 * HH + h] = v;
    if (dup) out[NTOT + n * TH + h] = v;
    if (blockIdx.x == 0 && threadIdx.x == 0) g_bar = 0u;
}

// ---------------------------------------------------------------------------
// Warp butterfly: reduce 32 per-lane partials across 32 lanes so that
// lane L ends up owning the full sum of original index L.
// ---------------------------------------------------------------------------
template <int OFF, int M>
__device__ __forceinline__ void red_round(float* acc, int lane)
{
    const bool up = (lane & OFF) != 0;
#pragma unroll
    for (int i = 0; i < M; i++) {
        float keep = up ? acc[i + M] : acc[i];
        float send = up ? acc[i]     : acc[i + M];
        float recv = __shfl_xor_sync(0xffffffffu, send, OFF);
        acc[i] = keep + recv;
    }
}

// ---------------------------------------------------------------------------
// Phase 3: persistent recurrence kernel.
// Grid: 128 CTAs = 16 row-groups (32 h-rows) x 8 batch-groups (4 batches).
// CTA: 256 threads = 4 row-subgroups (8 rows) x 64 k-chunks.
// Thread: rows r0..r0+7, batches n0..n0+3, k in {kc + 64*j, j=0..7}.
// W_hh slice pinned in registers (8x8 = 64 floats) for all 2047 steps.
// ---------------------------------------------------------------------------
__global__ void __launch_bounds__(256, 1) rnn_kernel(
    const float* __restrict__ W_hh,
    float* __restrict__ out, int dup)
{
    __shared__ float h_s[4 * HH];    // h_{t-1} for this CTA's 4 batches
    __shared__ float red[4][32];     // cross-warp partial combine

    const int tid  = threadIdx.x;
    const int kc   = tid & 63;       // k-chunk id (k = kc + 64*j)
    const int rsub = tid >> 6;       // 0..3
    const int bg   = blockIdx.x & 7; // batch group
    const int rg   = blockIdx.x >> 3;// row group
    const int n0   = bg * 4;
    const int r0   = rg * 32 + rsub * 8;
    const int lane = tid & 31;

    // Register-resident W_hh slice: w[r][j] = W_hh[(r0+r)*512 + kc + 64*j]
    float w[8][8];
#pragma unroll
    for (int r = 0; r < 8; r++)
#pragma unroll
        for (int j = 0; j < 8; j++)
            w[r][j] = W_hh[(r0 + r) * HH + kc + 64 * j];

    const bool writer = (kc < 32);           // warp0 of each rsub owns outputs
    const int  rl = lane >> 2;               // output row-local  (0..7)
    const int  nl = lane & 3;                // output batch-local(0..3)
    const int  outRow = r0 + rl;             // global h index of my output
    const int  outN   = n0 + nl;             // global batch of my output

    // fill-phase mapping: thread loads 8 consecutive h-floats of one batch
    const int ff  = tid * 8;                 // 0..2040
    const int fn  = ff >> 9;                 // batch-local 0..3
    const int fk  = ff & 511;                // k offset (multiple of 8)

    for (int t = 1; t < TT; t++) {
        // ---- stage h_{t-1} (written last step, globally visible via barrier)
        {
            const float4* src = reinterpret_cast<const float4*>(
                out + (n0 + fn) * TH + (t - 1) * HH + fk);
            float4 a = __ldcg(src);
            float4 c = __ldcg(src + 1);
            *reinterpret_cast<float4*>(&h_s[fn * HH + fk])     = a;
            *reinterpret_cast<float4*>(&h_s[fn * HH + fk + 4]) = c;
        }
        // ---- prefetch my xproj value (independent of h)
        float xpv = 0.0f;
        if (writer)
            xpv = __ldg(&g_xp[(outN * TT + (t - 1)) * HH + outRow]);
        __syncthreads();

        // ---- main FMA loop: 256 FMA, 32 LDS (conflict-free: bank = lane)
        float acc[32];
#pragma unroll
        for (int i = 0; i < 32; i++) acc[i] = 0.0f;
#pragma unroll
        for (int j = 0; j < 8; j++) {
            const int k = kc + 64 * j;
            const float h0v = h_s[0 * HH + k];
            const float h1v = h_s[1 * HH + k];
            const float h2v = h_s[2 * HH + k];
            const float h3v = h_s[3 * HH + k];
#pragma unroll
            for (int r = 0; r < 8; r++) {
                acc[r * 4 + 0] += w[r][j] * h0v;
                acc[r * 4 + 1] += w[r][j] * h1v;
                acc[r * 4 + 2] += w[r][j] * h2v;
                acc[r * 4 + 3] += w[r][j] * h3v;
            }
        }

        // ---- warp butterfly: lane L owns output index L (r = L>>2, n = L&3)
        red_round<16, 16>(acc, lane);
        red_round< 8,  8>(acc, lane);
        red_round< 4,  4>(acc, lane);
        red_round< 2,  2>(acc, lane);
        red_round< 1,  1>(acc, lane);

        // ---- cross-warp combine (kc>=32 half contributes via smem)
        if (!writer) red[rsub][lane] = acc[0];
        __syncthreads();

        if (writer) {
            const float v = acc[0] + red[rsub][lane] + xpv;
            const int oi = outN * TH + t * HH + outRow;
            out[oi] = v;
            if (dup) out[NTOT + oi] = v;
            __threadfence();   // release my h_t store to L2 (gpu scope)
        }
        __syncthreads();       // all writers fenced before the arrive

        // ---- chip-wide barrier (monotone counter; reset per launch)
        if (tid == 0) {
            atomicAdd(&g_bar, 1u);
            const unsigned target = (unsigned)t * NCTA;
            while (*((volatile unsigned*)&g_bar) < target) { }
        }
        __syncthreads();
    }
}

// ---------------------------------------------------------------------------
// Launch: inputs in metadata order: x, initial, W_ih, b_ih, W_hh
// ---------------------------------------------------------------------------
extern "C" void kernel_launch(void* const* d_in, const int* in_sizes, int n_in,
                              void* d_out, int out_size)
{
    const float* x       = (const float*)d_in[0];
    const float* initial = (const float*)d_in[1];
    const float* W_ih    = (const float*)d_in[2];
    const float* b_ih    = (const float*)d_in[3];
    const float* W_hh    = (const float*)d_in[4];
    float* out = (float*)d_out;
    const int dup = (out_size >= 2 * NTOT) ? 1 : 0;

    xproj_kernel<<<NT / 32, 512>>>(x, W_ih, b_ih);
    h0_kernel<<<NB, HH>>>(initial, out, dup);
    rnn_kernel<<<NCTA, 256>>>(W_hh, out, dup);
}